// round 6
// baseline (speedup 1.0000x reference)
#include <cuda_runtime.h>
#include <cuda_bf16.h>

#define FULL_MASK 0xFFFFFFFFu

// 4 lanes per row (8 bins each), 8 rows per warp.
// Per-warp smem staging of V (contiguous 264-float block) -> all global loads
// are coalesced float4; per-lane vertices come from conflict-free LDS.
__global__ __launch_bounds__(256)
void pwq_coupling_kernel(const float* __restrict__ x_b,
                         const float* __restrict__ W,
                         const float* __restrict__ V,
                         float* __restrict__ out,   // [0:n)=z, [n:2n)=log_det
                         int n)
{
    __shared__ float sV[8][264];               // one 264-float slice per warp

    const int lane   = threadIdx.x & 31;
    const int warpIn = threadIdx.x >> 5;
    const int t      = lane & 3;               // sublane within 4-lane segment
    const int rowIn  = lane >> 2;              // row within warp (0..7)
    const int warpGlobal = blockIdx.x * 8 + warpIn;
    const int row = warpGlobal * 8 + rowIn;
    if (row >= n) return;                      // n % 8 == 0 -> warp-uniform exit

    // ---- per-warp V staging: 66 aligned float4 loads, fully coalesced ----
    {
        const float4* __restrict__ Vq =
            (const float4*)(V + (size_t)warpGlobal * 264);
        float4* __restrict__ sq = (float4*)(sV[warpIn]);
        const float4 q0 = __ldcs(&Vq[lane]);
        const float4 q1 = __ldcs(&Vq[lane + 32]);
        sq[lane]      = q0;
        sq[lane + 32] = q1;
        if (lane < 2) sq[lane + 64] = __ldcs(&Vq[lane + 64]);
    }

    // ---- W + x loads (overlap staging latency) ----
    const float* __restrict__ Wrow = W + (size_t)row * 32 + t * 8;
    const float4 wa = __ldcs((const float4*)(Wrow));      // bins 8t..8t+3
    const float4 wb = __ldcs((const float4*)(Wrow + 4));  // bins 8t+4..8t+7
    const float  x  = x_b[row];                // 4 lanes same addr -> broadcast

    __syncwarp();

    // ---- 9 vertices from smem (bank = rowIn + 8t + k : conflict-free) ----
    const float* sv = sV[warpIn] + rowIn * 33 + t * 8;
    const float v0 = sv[0];
    const float v1 = sv[1];
    const float v2 = sv[2];
    const float v3 = sv[3];
    const float v4 = sv[4];
    const float v5 = sv[5];
    const float v6 = sv[6];
    const float v7 = sv[7];
    const float v8 = sv[8];

    // ---- local inclusive prefixes of widths ----
    const float pw1 = wa.x;
    const float pw2 = pw1 + wa.y;
    const float pw3 = pw2 + wa.z;
    const float pw4 = pw3 + wa.w;
    const float pw5 = pw4 + wb.x;
    const float pw6 = pw5 + wb.y;
    const float pw7 = pw6 + wb.z;
    const float pw8 = pw7 + wb.w;

    // ---- local inclusive prefixes of trapezoid areas ----
    const float pa1 = 0.5f * (v0 + v1) * wa.x;
    const float pa2 = pa1 + 0.5f * (v1 + v2) * wa.y;
    const float pa3 = pa2 + 0.5f * (v2 + v3) * wa.z;
    const float pa4 = pa3 + 0.5f * (v3 + v4) * wa.w;
    const float pa5 = pa4 + 0.5f * (v4 + v5) * wb.x;
    const float pa6 = pa5 + 0.5f * (v5 + v6) * wb.y;
    const float pa7 = pa6 + 0.5f * (v6 + v7) * wb.z;
    const float pa8 = pa7 + 0.5f * (v7 + v8) * wb.w;

    // ---- segmented 4-lane scan of segment totals ----
    float cw = pw8, ca = pa8;
    #pragma unroll
    for (int d = 1; d < 4; d <<= 1) {
        const float tw = __shfl_up_sync(FULL_MASK, cw, d, 4);
        const float ta = __shfl_up_sync(FULL_MASK, ca, d, 4);
        if (t >= d) { cw += tw; ca += ta; }
    }
    const float bw = cw - pw8;                 // left edge of bin 8t
    const float ba = ca - pa8;                 // CDF at left edge of bin 8t

    // ---- bin search: count interior edges <= val across the row ----
    const float val = fminf(fmaxf(x, 0.0f), 0.9999f);
    const float vb  = val - bw;                // segment-local coordinate
    int cnt = (int)(vb >= pw1) + (int)(vb >= pw2)
            + (int)(vb >= pw3) + (int)(vb >= pw4)
            + (int)(vb >= pw5) + (int)(vb >= pw6)
            + (int)(vb >= pw7) + (int)(vb >= pw8);
    cnt += __shfl_xor_sync(FULL_MASK, cnt, 1, 4);
    cnt += __shfl_xor_sync(FULL_MASK, cnt, 2, 4);
    const int bin = min(cnt, 31);

    // ---- owner lane finalizes ----
    if (t == (bin >> 3)) {
        const int j = bin & 7;
        // Cheap reloads: W from L1 (same line as above), V from smem.
        const float wj  = Wrow[j];
        const float vj  = sv[j];
        const float vj1 = sv[j + 1];

        // local exclusive prefixes at j (index 0 -> 0)
        const bool b1 = (j & 1), b2 = (j & 2), b4 = (j & 4);
        const float pwj = b4 ? (b2 ? (b1 ? pw7 : pw6) : (b1 ? pw5 : pw4))
                             : (b2 ? (b1 ? pw3 : pw2) : (b1 ? pw1 : 0.0f));
        const float paj = b4 ? (b2 ? (b1 ? pa7 : pa6) : (b1 ? pa5 : pa4))
                             : (b2 ? (b1 ? pa3 : pa2) : (b1 ? pa1 : 0.0f));

        const float edge_b = bw + pwj;
        const float alpha  = __fdividef(val - edge_b, wj + 1e-8f);
        const float dv     = vj1 - vj;
        const float z      = (ba + paj) + alpha * wj * (vj + 0.5f * alpha * dv);
        __stcs(&out[row], z);
        __stcs(&out[n + row], __logf(vj + alpha * dv + 1e-8f));
    }
}

extern "C" void kernel_launch(void* const* d_in, const int* in_sizes, int n_in,
                              void* d_out, int out_size)
{
    const float* x_b = (const float*)d_in[0];
    const float* W   = (const float*)d_in[1];
    const float* V   = (const float*)d_in[2];
    float* out = (float*)d_out;

    const int n = in_sizes[0];
    const int rowsPerBlock = 64;               // 8 warps * 8 rows
    const int blocks = (n + rowsPerBlock - 1) / rowsPerBlock;
    pwq_coupling_kernel<<<blocks, 256>>>(x_b, W, V, out, n);
}

// round 7
// speedup vs baseline: 1.0416x; 1.0416x over previous
#include <cuda_runtime.h>
#include <cuda_bf16.h>

#define FULL_MASK 0xFFFFFFFFu

// 4 lanes per row (8 bins each), 8 rows per group, 2 independent groups per
// warp (16 rows/warp) to double in-flight memory per warp.
__global__ __launch_bounds__(256)
void pwq_coupling_kernel(const float* __restrict__ x_b,
                         const float* __restrict__ W,
                         const float* __restrict__ V,
                         float* __restrict__ out,   // [0:n)=z, [n:2n)=log_det
                         int n)
{
    const int lane = threadIdx.x & 31;
    const int t    = lane & 3;                 // sublane within 4-lane segment
    const int warpGlobal = (blockIdx.x * blockDim.x + threadIdx.x) >> 5;
    const int row0 = warpGlobal * 16 + (lane >> 2);   // group 0 row
    const int row1 = row0 + 8;                        // group 1 row
    if (row0 >= n) return;                     // n % 16 == 0 -> warp-uniform

    const float* __restrict__ Wrow0 = W + (size_t)row0 * 32 + t * 8;
    const float* __restrict__ Vrow0 = V + (size_t)row0 * 33 + t * 8;
    const float* __restrict__ Wrow1 = W + (size_t)row1 * 32 + t * 8;
    const float* __restrict__ Vrow1 = V + (size_t)row1 * 33 + t * 8;

    // ================= issue ALL loads for both groups =================
    const float  x0  = x_b[row0];
    const float  x1  = x_b[row1];
    const float4 wa0 = *(const float4*)(Wrow0);
    const float4 wb0 = *(const float4*)(Wrow0 + 4);
    const float4 wa1 = *(const float4*)(Wrow1);
    const float4 wb1 = *(const float4*)(Wrow1 + 4);
    const float u0 = Vrow0[0], u1 = Vrow0[1], u2 = Vrow0[2], u3 = Vrow0[3];
    const float u4 = Vrow0[4], u5 = Vrow0[5], u6 = Vrow0[6], u7 = Vrow0[7];
    const float y0 = Vrow1[0], y1 = Vrow1[1], y2 = Vrow1[2], y3 = Vrow1[3];
    const float y4 = Vrow1[4], y5 = Vrow1[5], y6 = Vrow1[6], y7 = Vrow1[7];

    float u8 = __shfl_down_sync(FULL_MASK, u0, 1, 4);
    float y8 = __shfl_down_sync(FULL_MASK, y0, 1, 4);
    if (t == 3) { u8 = Vrow0[8]; y8 = Vrow1[8]; }

    // ================= group 0 compute (v/w regs die here) =============
    const float q1 = wa0.x;
    const float q2 = q1 + wa0.y;
    const float q3 = q2 + wa0.z;
    const float q4 = q3 + wa0.w;
    const float q5 = q4 + wb0.x;
    const float q6 = q5 + wb0.y;
    const float q7 = q6 + wb0.z;
    const float q8 = q7 + wb0.w;
    const float r1 = 0.5f * (u0 + u1) * wa0.x;
    const float r2 = r1 + 0.5f * (u1 + u2) * wa0.y;
    const float r3 = r2 + 0.5f * (u2 + u3) * wa0.z;
    const float r4 = r3 + 0.5f * (u3 + u4) * wa0.w;
    const float r5 = r4 + 0.5f * (u4 + u5) * wb0.x;
    const float r6 = r5 + 0.5f * (u5 + u6) * wb0.y;
    const float r7 = r6 + 0.5f * (u6 + u7) * wb0.z;
    const float r8 = r7 + 0.5f * (u7 + u8) * wb0.w;

    // ================= group 1 compute =================================
    const float s1 = wa1.x;
    const float s2 = s1 + wa1.y;
    const float s3 = s2 + wa1.z;
    const float s4 = s3 + wa1.w;
    const float s5 = s4 + wb1.x;
    const float s6 = s5 + wb1.y;
    const float s7 = s6 + wb1.z;
    const float s8 = s7 + wb1.w;
    const float m1 = 0.5f * (y0 + y1) * wa1.x;
    const float m2 = m1 + 0.5f * (y1 + y2) * wa1.y;
    const float m3 = m2 + 0.5f * (y2 + y3) * wa1.z;
    const float m4 = m3 + 0.5f * (y3 + y4) * wa1.w;
    const float m5 = m4 + 0.5f * (y4 + y5) * wb1.x;
    const float m6 = m5 + 0.5f * (y5 + y6) * wb1.y;
    const float m7 = m6 + 0.5f * (y6 + y7) * wb1.z;
    const float m8 = m7 + 0.5f * (y7 + y8) * wb1.w;

    // ============ segmented 4-lane scans, both groups interleaved ======
    float cw0 = q8, ca0 = r8, cw1 = s8, ca1 = m8;
    #pragma unroll
    for (int d = 1; d < 4; d <<= 1) {
        const float tw0 = __shfl_up_sync(FULL_MASK, cw0, d, 4);
        const float ta0 = __shfl_up_sync(FULL_MASK, ca0, d, 4);
        const float tw1 = __shfl_up_sync(FULL_MASK, cw1, d, 4);
        const float ta1 = __shfl_up_sync(FULL_MASK, ca1, d, 4);
        if (t >= d) { cw0 += tw0; ca0 += ta0; cw1 += tw1; ca1 += ta1; }
    }
    const float bw0 = cw0 - q8, ba0 = ca0 - r8;
    const float bw1 = cw1 - s8, ba1 = ca1 - m8;

    // ============ bin search, both groups ==============================
    const float val0 = fminf(fmaxf(x0, 0.0f), 0.9999f);
    const float val1 = fminf(fmaxf(x1, 0.0f), 0.9999f);
    const float vb0 = val0 - bw0;
    const float vb1 = val1 - bw1;
    int c0 = (int)(vb0 >= q1) + (int)(vb0 >= q2) + (int)(vb0 >= q3) + (int)(vb0 >= q4)
           + (int)(vb0 >= q5) + (int)(vb0 >= q6) + (int)(vb0 >= q7) + (int)(vb0 >= q8);
    int c1 = (int)(vb1 >= s1) + (int)(vb1 >= s2) + (int)(vb1 >= s3) + (int)(vb1 >= s4)
           + (int)(vb1 >= s5) + (int)(vb1 >= s6) + (int)(vb1 >= s7) + (int)(vb1 >= s8);
    // pack both counts into one value to halve the reduce shuffles
    int packed = c0 | (c1 << 8);
    packed += __shfl_xor_sync(FULL_MASK, packed, 1, 4);
    packed += __shfl_xor_sync(FULL_MASK, packed, 2, 4);
    const int bin0 = min(packed & 0xFF, 31);
    const int bin1 = min(packed >> 8, 31);

    // ============ owner-lane finalize, group 0 =========================
    if (t == (bin0 >> 3)) {
        const int j = bin0 & 7;
        const float wj  = Wrow0[j];            // L1 hit
        const float vj  = Vrow0[j];            // L1 hit
        const float vj1 = Vrow0[j + 1];        // L1 hit
        const bool b1 = (j & 1), b2 = (j & 2), b4 = (j & 4);
        const float pwj = b4 ? (b2 ? (b1 ? q7 : q6) : (b1 ? q5 : q4))
                             : (b2 ? (b1 ? q3 : q2) : (b1 ? q1 : 0.0f));
        const float paj = b4 ? (b2 ? (b1 ? r7 : r6) : (b1 ? r5 : r4))
                             : (b2 ? (b1 ? r3 : r2) : (b1 ? r1 : 0.0f));
        const float alpha = __fdividef(val0 - (bw0 + pwj), wj + 1e-8f);
        const float dv    = vj1 - vj;
        out[row0]     = (ba0 + paj) + alpha * wj * (vj + 0.5f * alpha * dv);
        out[n + row0] = __logf(vj + alpha * dv + 1e-8f);
    }

    // ============ owner-lane finalize, group 1 =========================
    if (t == (bin1 >> 3)) {
        const int j = bin1 & 7;
        const float wj  = Wrow1[j];
        const float vj  = Vrow1[j];
        const float vj1 = Vrow1[j + 1];
        const bool b1 = (j & 1), b2 = (j & 2), b4 = (j & 4);
        const float pwj = b4 ? (b2 ? (b1 ? s7 : s6) : (b1 ? s5 : s4))
                             : (b2 ? (b1 ? s3 : s2) : (b1 ? s1 : 0.0f));
        const float paj = b4 ? (b2 ? (b1 ? m7 : m6) : (b1 ? m5 : m4))
                             : (b2 ? (b1 ? m3 : m2) : (b1 ? m1 : 0.0f));
        const float alpha = __fdividef(val1 - (bw1 + pwj), wj + 1e-8f);
        const float dv    = vj1 - vj;
        out[row1]     = (ba1 + paj) + alpha * wj * (vj + 0.5f * alpha * dv);
        out[n + row1] = __logf(vj + alpha * dv + 1e-8f);
    }
}

extern "C" void kernel_launch(void* const* d_in, const int* in_sizes, int n_in,
                              void* d_out, int out_size)
{
    const float* x_b = (const float*)d_in[0];
    const float* W   = (const float*)d_in[1];
    const float* V   = (const float*)d_in[2];
    float* out = (float*)d_out;

    const int n = in_sizes[0];
    const int rowsPerBlock = 128;              // 8 warps * 16 rows
    const int blocks = (n + rowsPerBlock - 1) / rowsPerBlock;
    pwq_coupling_kernel<<<blocks, 256>>>(x_b, W, V, out, n);
}